// round 3
// baseline (speedup 1.0000x reference)
#include <cuda_runtime.h>
#include <cuda_bf16.h>
#include <stdint.h>

// Edge MLP: out[e] = sigmoid( relu( relu( [src|dst] @ W1 + b1 ) @ W2 + b2 ) @ W3 + b3 )
// node_rep: [N,64] f32, edge_index: [2,E] int32 (JAX default x64-disabled downcasts i64->i32),
// W1:[128,128], W2:[128,128], W3:[128,1]
//
// Strategy: persistent CTAs, 128-edge tiles, bf16 warp-MMA (m16n8k16), fp32 accum.
// Weights transposed to SMEM once per CTA. GEMM1 C-frags == GEMM2 A-frags (register reuse).

#define FEAT 128
#define HID 128
#define TILE_M 128
#define SW 136          // shared stride in bf16 elements (68 words -> bank = lane, conflict-free)
#define THREADS 256
#define NWARP 8

__device__ __forceinline__ unsigned pack_bf16(float a, float b) {
    // packed bf16x2: low half = a, high half = b
    unsigned r;
    asm("cvt.rn.bf16x2.f32 %0, %1, %2;" : "=r"(r) : "f"(b), "f"(a));
    return r;
}

__device__ __forceinline__ void mma16816(float c[4],
                                         unsigned a0, unsigned a1, unsigned a2, unsigned a3,
                                         unsigned b0, unsigned b1) {
    asm volatile(
        "mma.sync.aligned.m16n8k16.row.col.f32.bf16.bf16.f32 "
        "{%0,%1,%2,%3}, {%4,%5,%6,%7}, {%8,%9}, {%0,%1,%2,%3};\n"
        : "+f"(c[0]), "+f"(c[1]), "+f"(c[2]), "+f"(c[3])
        : "r"(a0), "r"(a1), "r"(a2), "r"(a3), "r"(b0), "r"(b1));
}

// dynamic smem layout (bytes):
//   w1t: 128*SW bf16   (transposed: w1t[n*SW+k] = W1[k][n])
//   w2t: 128*SW bf16
//   feat: 128*SW bf16  (feat[row*SW + c], c<64 = src feats, c>=64 = dst feats)
//   b1s, b2s, w3s: 128 f32 each
#define SMEM_W1T   0
#define SMEM_W2T   (128 * SW)
#define SMEM_FEAT  (2 * 128 * SW)
#define SMEM_BF16_TOTAL (3 * 128 * SW)
#define SMEM_F32_OFF (SMEM_BF16_TOTAL * 2)                 // byte offset of f32 section
#define SMEM_BYTES  (SMEM_F32_OFF + 3 * 128 * 4)

extern "C" __global__ void __launch_bounds__(THREADS, 2)
graphormer_edge_mlp(const float* __restrict__ node_rep,
                    const int* __restrict__ eidx,
                    const float* __restrict__ W1, const float* __restrict__ b1,
                    const float* __restrict__ W2, const float* __restrict__ b2,
                    const float* __restrict__ W3, const float* __restrict__ b3,
                    float* __restrict__ out,
                    int E, int num_tiles) {
    extern __shared__ char smem_raw[];
    __nv_bfloat16* w1t  = reinterpret_cast<__nv_bfloat16*>(smem_raw) + SMEM_W1T;
    __nv_bfloat16* w2t  = reinterpret_cast<__nv_bfloat16*>(smem_raw) + SMEM_W2T;
    __nv_bfloat16* feat = reinterpret_cast<__nv_bfloat16*>(smem_raw) + SMEM_FEAT;
    float* b1s = reinterpret_cast<float*>(smem_raw + SMEM_F32_OFF);
    float* b2s = b1s + 128;
    float* w3s = b2s + 128;

    const int tid  = threadIdx.x;
    const int lane = tid & 31;
    const int warp = tid >> 5;

    // ---- one-time per CTA: weights (transposed, bf16), biases ----
    for (int i = tid; i < 128 * 128; i += THREADS) {
        int k = i >> 7, n = i & 127;
        w1t[n * SW + k] = __float2bfloat16(W1[i]);
        w2t[n * SW + k] = __float2bfloat16(W2[i]);
    }
    if (tid < 128) { b1s[tid] = b1[tid]; b2s[tid] = b2[tid]; w3s[tid] = W3[tid]; }
    const float bb3 = b3[0];
    __syncthreads();

    const int q  = lane & 3;        // thread-in-group
    const int g4 = lane >> 2;       // group id 0..7
    const int r0 = (warp << 4) + g4;  // first row (edge-in-tile) this thread owns

    for (int tile = blockIdx.x; tile < num_tiles; tile += gridDim.x) {
        const int base = tile * TILE_M;

        // ---- gather: 16 threads cooperate per 256B node row (fully coalesced) ----
        {
            const int grp = tid >> 4, l16 = tid & 15;
            #pragma unroll
            for (int h = grp; h < 2 * TILE_M; h += 16) {
                const int edge = h >> 1, half = h & 1;
                const int e = base + edge;
                int node = 0;
                if (e < E) node = eidx[half * E + e];
                float4 v = reinterpret_cast<const float4*>(node_rep + (long long)node * 64)[l16];
                unsigned* d32 = reinterpret_cast<unsigned*>(feat + edge * SW + half * 64 + l16 * 4);
                d32[0] = pack_bf16(v.x, v.y);
                d32[1] = pack_bf16(v.z, v.w);
            }
        }
        __syncthreads();

        // ---- GEMM1: [128,128](feat) @ W1 -> acc[16 n8-tiles][4] per thread ----
        float acc[16][4];
        #pragma unroll
        for (int t = 0; t < 16; t++)
            #pragma unroll
            for (int j = 0; j < 4; j++) acc[t][j] = 0.f;

        #pragma unroll
        for (int kt = 0; kt < 8; kt++) {
            const int kc = kt * 16 + 2 * q;
            const unsigned a0 = *reinterpret_cast<const unsigned*>(feat + r0 * SW + kc);
            const unsigned a1 = *reinterpret_cast<const unsigned*>(feat + (r0 + 8) * SW + kc);
            const unsigned a2 = *reinterpret_cast<const unsigned*>(feat + r0 * SW + kc + 8);
            const unsigned a3 = *reinterpret_cast<const unsigned*>(feat + (r0 + 8) * SW + kc + 8);
            #pragma unroll
            for (int t = 0; t < 16; t++) {
                const int n = t * 8 + g4;
                const unsigned b0 = *reinterpret_cast<const unsigned*>(w1t + n * SW + kc);
                const unsigned b1r = *reinterpret_cast<const unsigned*>(w1t + n * SW + kc + 8);
                mma16816(acc[t], a0, a1, a2, a3, b0, b1r);
            }
        }

        // ---- epilogue1: bias + relu + pack -> A-fragments for GEMM2 (register-only) ----
        // C frag (rows r0, r0+8; cols 8t+2q,+1) maps exactly onto A frag of k-tile t/2.
        unsigned ah[8][4];
        #pragma unroll
        for (int kt = 0; kt < 8; kt++) {
            #pragma unroll
            for (int s = 0; s < 2; s++) {
                const int t = 2 * kt + s;
                const int c = t * 8 + 2 * q;
                const float x0 = fmaxf(acc[t][0] + b1s[c], 0.f);
                const float x1 = fmaxf(acc[t][1] + b1s[c + 1], 0.f);
                const float x2 = fmaxf(acc[t][2] + b1s[c], 0.f);
                const float x3 = fmaxf(acc[t][3] + b1s[c + 1], 0.f);
                ah[kt][2 * s]     = pack_bf16(x0, x1);   // rows r0
                ah[kt][2 * s + 1] = pack_bf16(x2, x3);   // rows r0+8
            }
        }

        // ---- GEMM2: h1 @ W2 (A from registers) ----
        #pragma unroll
        for (int t = 0; t < 16; t++)
            #pragma unroll
            for (int j = 0; j < 4; j++) acc[t][j] = 0.f;

        #pragma unroll
        for (int kt = 0; kt < 8; kt++) {
            const int kc = kt * 16 + 2 * q;
            #pragma unroll
            for (int t = 0; t < 16; t++) {
                const int n = t * 8 + g4;
                const unsigned b0 = *reinterpret_cast<const unsigned*>(w2t + n * SW + kc);
                const unsigned b1r = *reinterpret_cast<const unsigned*>(w2t + n * SW + kc + 8);
                mma16816(acc[t], ah[kt][0], ah[kt][1], ah[kt][2], ah[kt][3], b0, b1r);
            }
        }

        // ---- epilogue2: bias + relu + dot(W3) + cross-lane reduce + sigmoid ----
        float d0 = 0.f, d1 = 0.f;   // rows r0 and r0+8
        #pragma unroll
        for (int t = 0; t < 16; t++) {
            const int c = t * 8 + 2 * q;
            const float wa = w3s[c], wb = w3s[c + 1];
            const float h0 = fmaxf(acc[t][0] + b2s[c], 0.f);
            const float h1 = fmaxf(acc[t][1] + b2s[c + 1], 0.f);
            const float h2 = fmaxf(acc[t][2] + b2s[c], 0.f);
            const float h3 = fmaxf(acc[t][3] + b2s[c + 1], 0.f);
            d0 += h0 * wa + h1 * wb;
            d1 += h2 * wa + h3 * wb;
        }
        d0 += __shfl_xor_sync(0xFFFFFFFFu, d0, 1);
        d0 += __shfl_xor_sync(0xFFFFFFFFu, d0, 2);
        d1 += __shfl_xor_sync(0xFFFFFFFFu, d1, 1);
        d1 += __shfl_xor_sync(0xFFFFFFFFu, d1, 2);

        if (q == 0) {
            const int e0 = base + r0;
            const int e1 = base + r0 + 8;
            if (e0 < E) out[e0] = 1.f / (1.f + __expf(-(d0 + bb3)));
            if (e1 < E) out[e1] = 1.f / (1.f + __expf(-(d1 + bb3)));
        }
        __syncthreads();   // protect feat before next tile's gather
    }
}

extern "C" void kernel_launch(void* const* d_in, const int* in_sizes, int n_in,
                              void* d_out, int out_size) {
    const float* node_rep = (const float*)d_in[0];
    const int*   eidx     = (const int*)d_in[1];      // int32: JAX default config downcasts int64
    const float* W1       = (const float*)d_in[2];
    const float* b1       = (const float*)d_in[3];
    const float* W2       = (const float*)d_in[4];
    const float* b2       = (const float*)d_in[5];
    const float* W3       = (const float*)d_in[6];
    const float* b3       = (const float*)d_in[7];
    float*       out      = (float*)d_out;

    const int E = in_sizes[1] / 2;
    const int num_tiles = (E + TILE_M - 1) / TILE_M;

    cudaFuncSetAttribute(graphormer_edge_mlp,
                         cudaFuncAttributeMaxDynamicSharedMemorySize, SMEM_BYTES);

    int grid = num_tiles < 592 ? num_tiles : 592;
    graphormer_edge_mlp<<<grid, THREADS, SMEM_BYTES>>>(
        node_rep, eidx, W1, b1, W2, b2, W3, b3, out, E, num_tiles);
}

// round 4
// speedup vs baseline: 1.1036x; 1.1036x over previous
#include <cuda_runtime.h>
#include <cuda_bf16.h>
#include <stdint.h>

// Edge MLP: out[e] = sigmoid( relu( relu( [src|dst] @ W1 + b1 ) @ W2 + b2 ) @ W3 + b3 )
// node_rep: [N,64] f32, edge_index: [2,E] int32, W1:[128,128], W2:[128,128], W3:[128,1]
//
// R4: 4 warps/CTA, each warp computes M=32 rows (two m16 blocks) so every B-fragment
// LDS is reused by 2 MMAs -> B SMEM traffic halved vs R3 (which was L1-bound at 68%).

#define TILE_M 128
#define SW 136          // shared stride in bf16 elems -> conflict-free B/A loads
#define THREADS 128
#define NWARP 4

__device__ __forceinline__ unsigned pack_bf16(float a, float b) {
    unsigned r;
    asm("cvt.rn.bf16x2.f32 %0, %1, %2;" : "=r"(r) : "f"(b), "f"(a));
    return r;
}

__device__ __forceinline__ void mma16816(float c[4],
                                         unsigned a0, unsigned a1, unsigned a2, unsigned a3,
                                         unsigned b0, unsigned b1) {
    asm volatile(
        "mma.sync.aligned.m16n8k16.row.col.f32.bf16.bf16.f32 "
        "{%0,%1,%2,%3}, {%4,%5,%6,%7}, {%8,%9}, {%0,%1,%2,%3};\n"
        : "+f"(c[0]), "+f"(c[1]), "+f"(c[2]), "+f"(c[3])
        : "r"(a0), "r"(a1), "r"(a2), "r"(a3), "r"(b0), "r"(b1));
}

#define SMEM_W1T   0
#define SMEM_W2T   (128 * SW)
#define SMEM_FEAT  (2 * 128 * SW)
#define SMEM_BF16_TOTAL (3 * 128 * SW)
#define SMEM_F32_OFF (SMEM_BF16_TOTAL * 2)
#define SMEM_BYTES  (SMEM_F32_OFF + 3 * 128 * 4)

extern "C" __global__ void __launch_bounds__(THREADS, 2)
graphormer_edge_mlp(const float* __restrict__ node_rep,
                    const int* __restrict__ eidx,
                    const float* __restrict__ W1, const float* __restrict__ b1,
                    const float* __restrict__ W2, const float* __restrict__ b2,
                    const float* __restrict__ W3, const float* __restrict__ b3,
                    float* __restrict__ out,
                    int E, int num_tiles) {
    extern __shared__ char smem_raw[];
    __nv_bfloat16* w1t  = reinterpret_cast<__nv_bfloat16*>(smem_raw) + SMEM_W1T;
    __nv_bfloat16* w2t  = reinterpret_cast<__nv_bfloat16*>(smem_raw) + SMEM_W2T;
    __nv_bfloat16* feat = reinterpret_cast<__nv_bfloat16*>(smem_raw) + SMEM_FEAT;
    float* b1s = reinterpret_cast<float*>(smem_raw + SMEM_F32_OFF);
    float* b2s = b1s + 128;
    float* w3s = b2s + 128;

    const int tid  = threadIdx.x;
    const int lane = tid & 31;
    const int warp = tid >> 5;

    // ---- one-time per CTA: weights (transposed, bf16), biases ----
    for (int i = tid; i < 128 * 128; i += THREADS) {
        int k = i >> 7, n = i & 127;
        w1t[n * SW + k] = __float2bfloat16(W1[i]);
        w2t[n * SW + k] = __float2bfloat16(W2[i]);
    }
    if (tid < 128) { b1s[tid] = b1[tid]; b2s[tid] = b2[tid]; w3s[tid] = W3[tid]; }
    const float bb3 = b3[0];
    __syncthreads();

    const int q  = lane & 3;          // thread-in-group
    const int g4 = lane >> 2;         // group id 0..7
    const int r0 = (warp << 5) + g4;  // first row of block 0 (warp owns rows warp*32..+31)

    for (int tile = blockIdx.x; tile < num_tiles; tile += gridDim.x) {
        const int base = tile * TILE_M;

        // ---- gather: 16 threads per 256B node row, 8 groups ----
        {
            const int grp = tid >> 4, l16 = tid & 15;
            #pragma unroll
            for (int h = grp; h < 2 * TILE_M; h += THREADS / 16) {
                const int edge = h >> 1, half = h & 1;
                const int e = base + edge;
                int node = 0;
                if (e < E) node = eidx[half * E + e];
                float4 v = reinterpret_cast<const float4*>(node_rep + (long long)node * 64)[l16];
                unsigned* d32 = reinterpret_cast<unsigned*>(feat + edge * SW + half * 64 + l16 * 4);
                d32[0] = pack_bf16(v.x, v.y);
                d32[1] = pack_bf16(v.z, v.w);
            }
        }
        __syncthreads();

        // ---- GEMM1: feat[128,128] @ W1; warp does 2 m16 blocks sharing B frags ----
        float acc[2][16][4];
        #pragma unroll
        for (int b = 0; b < 2; b++)
            #pragma unroll
            for (int t = 0; t < 16; t++)
                #pragma unroll
                for (int j = 0; j < 4; j++) acc[b][t][j] = 0.f;

        #pragma unroll
        for (int kt = 0; kt < 8; kt++) {
            const int kc = kt * 16 + 2 * q;
            unsigned a[2][4];
            #pragma unroll
            for (int b = 0; b < 2; b++) {
                const int rb = r0 + 16 * b;
                a[b][0] = *reinterpret_cast<const unsigned*>(feat + rb * SW + kc);
                a[b][1] = *reinterpret_cast<const unsigned*>(feat + (rb + 8) * SW + kc);
                a[b][2] = *reinterpret_cast<const unsigned*>(feat + rb * SW + kc + 8);
                a[b][3] = *reinterpret_cast<const unsigned*>(feat + (rb + 8) * SW + kc + 8);
            }
            #pragma unroll
            for (int t = 0; t < 16; t++) {
                const int n = t * 8 + g4;
                const unsigned b0 = *reinterpret_cast<const unsigned*>(w1t + n * SW + kc);
                const unsigned b1r = *reinterpret_cast<const unsigned*>(w1t + n * SW + kc + 8);
                mma16816(acc[0][t], a[0][0], a[0][1], a[0][2], a[0][3], b0, b1r);
                mma16816(acc[1][t], a[1][0], a[1][1], a[1][2], a[1][3], b0, b1r);
            }
        }

        // ---- epilogue1: bias + relu + pack -> A frags for GEMM2 (registers) ----
        unsigned ah[2][8][4];
        #pragma unroll
        for (int b = 0; b < 2; b++)
            #pragma unroll
            for (int kt = 0; kt < 8; kt++)
                #pragma unroll
                for (int s = 0; s < 2; s++) {
                    const int t = 2 * kt + s;
                    const int c = t * 8 + 2 * q;
                    const float x0 = fmaxf(acc[b][t][0] + b1s[c], 0.f);
                    const float x1 = fmaxf(acc[b][t][1] + b1s[c + 1], 0.f);
                    const float x2 = fmaxf(acc[b][t][2] + b1s[c], 0.f);
                    const float x3 = fmaxf(acc[b][t][3] + b1s[c + 1], 0.f);
                    ah[b][kt][2 * s]     = pack_bf16(x0, x1);
                    ah[b][kt][2 * s + 1] = pack_bf16(x2, x3);
                }

        // ---- GEMM2: h1 @ W2 (A from registers, B shared across blocks) ----
        #pragma unroll
        for (int b = 0; b < 2; b++)
            #pragma unroll
            for (int t = 0; t < 16; t++)
                #pragma unroll
                for (int j = 0; j < 4; j++) acc[b][t][j] = 0.f;

        #pragma unroll
        for (int kt = 0; kt < 8; kt++) {
            const int kc = kt * 16 + 2 * q;
            #pragma unroll
            for (int t = 0; t < 16; t++) {
                const int n = t * 8 + g4;
                const unsigned b0 = *reinterpret_cast<const unsigned*>(w2t + n * SW + kc);
                const unsigned b1r = *reinterpret_cast<const unsigned*>(w2t + n * SW + kc + 8);
                mma16816(acc[0][t], ah[0][kt][0], ah[0][kt][1], ah[0][kt][2], ah[0][kt][3], b0, b1r);
                mma16816(acc[1][t], ah[1][kt][0], ah[1][kt][1], ah[1][kt][2], ah[1][kt][3], b0, b1r);
            }
        }

        // ---- epilogue2: bias + relu + dot(W3) + lane reduce + sigmoid ----
        #pragma unroll
        for (int b = 0; b < 2; b++) {
            float d0 = 0.f, d1 = 0.f;
            #pragma unroll
            for (int t = 0; t < 16; t++) {
                const int c = t * 8 + 2 * q;
                const float wa = w3s[c], wb = w3s[c + 1];
                const float h0 = fmaxf(acc[b][t][0] + b2s[c], 0.f);
                const float h1 = fmaxf(acc[b][t][1] + b2s[c + 1], 0.f);
                const float h2 = fmaxf(acc[b][t][2] + b2s[c], 0.f);
                const float h3 = fmaxf(acc[b][t][3] + b2s[c + 1], 0.f);
                d0 += h0 * wa + h1 * wb;
                d1 += h2 * wa + h3 * wb;
            }
            d0 += __shfl_xor_sync(0xFFFFFFFFu, d0, 1);
            d0 += __shfl_xor_sync(0xFFFFFFFFu, d0, 2);
            d1 += __shfl_xor_sync(0xFFFFFFFFu, d1, 1);
            d1 += __shfl_xor_sync(0xFFFFFFFFu, d1, 2);
            if (q == 0) {
                const int e0 = base + r0 + 16 * b;
                const int e1 = e0 + 8;
                if (e0 < E) out[e0] = 1.f / (1.f + __expf(-(d0 + bb3)));
                if (e1 < E) out[e1] = 1.f / (1.f + __expf(-(d1 + bb3)));
            }
        }
        __syncthreads();   // protect feat before next tile's gather
    }
}

extern "C" void kernel_launch(void* const* d_in, const int* in_sizes, int n_in,
                              void* d_out, int out_size) {
    const float* node_rep = (const float*)d_in[0];
    const int*   eidx     = (const int*)d_in[1];
    const float* W1       = (const float*)d_in[2];
    const float* b1       = (const float*)d_in[3];
    const float* W2       = (const float*)d_in[4];
    const float* b2       = (const float*)d_in[5];
    const float* W3       = (const float*)d_in[6];
    const float* b3       = (const float*)d_in[7];
    float*       out      = (float*)d_out;

    const int E = in_sizes[1] / 2;
    const int num_tiles = (E + TILE_M - 1) / TILE_M;

    cudaFuncSetAttribute(graphormer_edge_mlp,
                         cudaFuncAttributeMaxDynamicSharedMemorySize, SMEM_BYTES);

    int grid = num_tiles < 296 ? num_tiles : 296;
    graphormer_edge_mlp<<<grid, THREADS, SMEM_BYTES>>>(
        node_rep, eidx, W1, b1, W2, b2, W3, b3, out, E, num_tiles);
}

// round 6
// speedup vs baseline: 1.1487x; 1.0409x over previous
#include <cuda_runtime.h>
#include <cuda_bf16.h>
#include <stdint.h>

// Edge MLP, factored: h1[e] = relu(P[src]+Q[dst]+b1) with P=node@W1[:64], Q=node@W1[64:]
// precomputed per NODE (100K) instead of per EDGE (1M)  -> GEMM1 work cut 10x.
// Main kernel: gather P/Q rows -> h1 tile -> GEMM2 (bf16 HMMA) -> dot(W3) -> sigmoid.

#define TILE_M 128
#define SW 136            // weight/feat smem stride (bf16 elems), conflict-free
#define SWA 72            // A-tile stride in precompute, conflict-free
#define THREADS 128
#define MAX_NODES 100352

__device__ __nv_bfloat16 g_P[(size_t)MAX_NODES * 128];
__device__ __nv_bfloat16 g_Q[(size_t)MAX_NODES * 128];

__device__ __forceinline__ unsigned pack_bf16(float lo, float hi) {
    unsigned r;
    asm("cvt.rn.bf16x2.f32 %0, %1, %2;" : "=r"(r) : "f"(hi), "f"(lo));
    return r;
}
__device__ __forceinline__ float bf16_lo(unsigned u) {
    return __bfloat162float(*reinterpret_cast<__nv_bfloat16*>(&u));
}
__device__ __forceinline__ float bf16_hi(unsigned u) {
    unsigned h = u >> 16;
    return __bfloat162float(*reinterpret_cast<__nv_bfloat16*>(&h));
}

__device__ __forceinline__ void mma16816(float c[4],
                                         unsigned a0, unsigned a1, unsigned a2, unsigned a3,
                                         unsigned b0, unsigned b1) {
    asm volatile(
        "mma.sync.aligned.m16n8k16.row.col.f32.bf16.bf16.f32 "
        "{%0,%1,%2,%3}, {%4,%5,%6,%7}, {%8,%9}, {%0,%1,%2,%3};\n"
        : "+f"(c[0]), "+f"(c[1]), "+f"(c[2]), "+f"(c[3])
        : "r"(a0), "r"(a1), "r"(a2), "r"(a3), "r"(b0), "r"(b1));
}

// ---------------- precompute: P/Q = node_rep @ W1 halves ----------------
// smem: w1t [128][SW] bf16 (w1t[n*SW+k] = W1[k][n]); a [128][SWA] bf16 (node tile)
#define PQ_SMEM_A   (128 * SW * 2)
#define PQ_SMEM     (PQ_SMEM_A + 128 * SWA * 2)

extern "C" __global__ void __launch_bounds__(THREADS, 3)
pq_precompute(const float* __restrict__ node_rep, const float* __restrict__ W1,
              int N, int ntiles) {
    extern __shared__ char smem_raw[];
    __nv_bfloat16* w1t = reinterpret_cast<__nv_bfloat16*>(smem_raw);
    __nv_bfloat16* a   = reinterpret_cast<__nv_bfloat16*>(smem_raw + PQ_SMEM_A);

    const int tid  = threadIdx.x;
    const int lane = tid & 31;
    const int warp = tid >> 5;

    for (int i = tid; i < 128 * 128; i += THREADS) {
        int k = i >> 7, n = i & 127;
        w1t[n * SW + k] = __float2bfloat16(W1[i]);
    }
    __syncthreads();

    const int q  = lane & 3;
    const int g4 = lane >> 2;
    const int r0 = (warp << 5) + g4;

    for (int tile = blockIdx.x; tile < ntiles; tile += gridDim.x) {
        const int base = tile * 128;

        // load node tile [128 rows][64 f32] -> bf16 smem
        for (int idx = tid; idx < 128 * 16; idx += THREADS) {
            const int row = idx >> 4, seg = idx & 15;
            int node = base + row; if (node >= N) node = N - 1;
            const float4 v = reinterpret_cast<const float4*>(node_rep + (long long)node * 64)[seg];
            const unsigned w0 = pack_bf16(v.x, v.y);
            const unsigned w1p = pack_bf16(v.z, v.w);
            uint64_t dv = ((uint64_t)w1p << 32) | w0;
            *reinterpret_cast<uint64_t*>(a + row * SWA + seg * 4) = dv;
        }
        __syncthreads();

        #pragma unroll
        for (int h = 0; h < 2; h++) {
            float acc[2][16][4];
            #pragma unroll
            for (int b = 0; b < 2; b++)
                #pragma unroll
                for (int t = 0; t < 16; t++)
                    #pragma unroll
                    for (int j = 0; j < 4; j++) acc[b][t][j] = 0.f;

            #pragma unroll
            for (int kt = 0; kt < 4; kt++) {
                const int kc = kt * 16 + 2 * q;
                unsigned af[2][4];
                #pragma unroll
                for (int b = 0; b < 2; b++) {
                    const int rb = r0 + 16 * b;
                    af[b][0] = *reinterpret_cast<const unsigned*>(a + rb * SWA + kc);
                    af[b][1] = *reinterpret_cast<const unsigned*>(a + (rb + 8) * SWA + kc);
                    af[b][2] = *reinterpret_cast<const unsigned*>(a + rb * SWA + kc + 8);
                    af[b][3] = *reinterpret_cast<const unsigned*>(a + (rb + 8) * SWA + kc + 8);
                }
                #pragma unroll
                for (int t = 0; t < 16; t++) {
                    const int n = t * 8 + g4;
                    const unsigned b0 = *reinterpret_cast<const unsigned*>(w1t + n * SW + 64 * h + kc);
                    const unsigned b1r = *reinterpret_cast<const unsigned*>(w1t + n * SW + 64 * h + kc + 8);
                    mma16816(acc[0][t], af[0][0], af[0][1], af[0][2], af[0][3], b0, b1r);
                    mma16816(acc[1][t], af[1][0], af[1][1], af[1][2], af[1][3], b0, b1r);
                }
            }

            __nv_bfloat16* outp = h ? g_Q : g_P;
            #pragma unroll
            for (int b = 0; b < 2; b++) {
                const int n0 = base + r0 + 16 * b;
                #pragma unroll
                for (int t = 0; t < 16; t++) {
                    const int c = t * 8 + 2 * q;
                    if (n0 < N)
                        *reinterpret_cast<unsigned*>(outp + (long long)n0 * 128 + c) =
                            pack_bf16(acc[b][t][0], acc[b][t][1]);
                    if (n0 + 8 < N)
                        *reinterpret_cast<unsigned*>(outp + (long long)(n0 + 8) * 128 + c) =
                            pack_bf16(acc[b][t][2], acc[b][t][3]);
                }
            }
        }
        __syncthreads();
    }
}

// ---------------- main: h1 build + GEMM2 + dot(W3) ----------------
// smem: w2t [128][SW] bf16; feat(h1) [128][SW] bf16; b1s,b2s,w3s f32[128]
#define SM_W2   0
#define SM_FEAT (128 * SW * 2)
#define SM_F32  (2 * 128 * SW * 2)
#define SMEM_BYTES (SM_F32 + 3 * 128 * 4)

extern "C" __global__ void __launch_bounds__(THREADS, 3)
graphormer_edge_mlp(const int* __restrict__ eidx,
                    const float* __restrict__ b1,
                    const float* __restrict__ W2, const float* __restrict__ b2,
                    const float* __restrict__ W3, const float* __restrict__ b3,
                    float* __restrict__ out,
                    int E, int num_tiles) {
    extern __shared__ char smem_raw[];
    __nv_bfloat16* w2t  = reinterpret_cast<__nv_bfloat16*>(smem_raw + SM_W2);
    __nv_bfloat16* feat = reinterpret_cast<__nv_bfloat16*>(smem_raw + SM_FEAT);
    float* b1s = reinterpret_cast<float*>(smem_raw + SM_F32);
    float* b2s = b1s + 128;
    float* w3s = b2s + 128;

    const int tid  = threadIdx.x;
    const int lane = tid & 31;
    const int warp = tid >> 5;

    for (int i = tid; i < 128 * 128; i += THREADS) {
        int k = i >> 7, n = i & 127;
        w2t[n * SW + k] = __float2bfloat16(W2[i]);
    }
    if (tid < 128) { b1s[tid] = b1[tid]; b2s[tid] = b2[tid]; w3s[tid] = W3[tid]; }
    const float bb3 = b3[0];
    __syncthreads();

    const int q  = lane & 3;
    const int g4 = lane >> 2;
    const int r0 = (warp << 5) + g4;

    for (int tile = blockIdx.x; tile < num_tiles; tile += gridDim.x) {
        const int base = tile * TILE_M;

        // ---- h1 build: 16 threads per edge; each handles 8 cols ----
        {
            const int grp = tid >> 4, l16 = tid & 15;
            #pragma unroll
            for (int edge = grp; edge < TILE_M; edge += THREADS / 16) {
                const int e = base + edge;
                int src = 0, dst = 0;
                if (e < E) { src = eidx[e]; dst = eidx[E + e]; }
                const uint4 pv = reinterpret_cast<const uint4*>(g_P + (long long)src * 128)[l16];
                const uint4 qv = reinterpret_cast<const uint4*>(g_Q + (long long)dst * 128)[l16];
                const float* bb = b1s + l16 * 8;
                uint4 o;
                o.x = pack_bf16(fmaxf(bf16_lo(pv.x) + bf16_lo(qv.x) + bb[0], 0.f),
                                fmaxf(bf16_hi(pv.x) + bf16_hi(qv.x) + bb[1], 0.f));
                o.y = pack_bf16(fmaxf(bf16_lo(pv.y) + bf16_lo(qv.y) + bb[2], 0.f),
                                fmaxf(bf16_hi(pv.y) + bf16_hi(qv.y) + bb[3], 0.f));
                o.z = pack_bf16(fmaxf(bf16_lo(pv.z) + bf16_lo(qv.z) + bb[4], 0.f),
                                fmaxf(bf16_hi(pv.z) + bf16_hi(qv.z) + bb[5], 0.f));
                o.w = pack_bf16(fmaxf(bf16_lo(pv.w) + bf16_lo(qv.w) + bb[6], 0.f),
                                fmaxf(bf16_hi(pv.w) + bf16_hi(qv.w) + bb[7], 0.f));
                *reinterpret_cast<uint4*>(feat + edge * SW + l16 * 8) = o;
            }
        }
        __syncthreads();

        // ---- GEMM2: h1[128,128] @ W2; warp does 2 m16 blocks sharing B frags ----
        float acc[2][16][4];
        #pragma unroll
        for (int b = 0; b < 2; b++)
            #pragma unroll
            for (int t = 0; t < 16; t++)
                #pragma unroll
                for (int j = 0; j < 4; j++) acc[b][t][j] = 0.f;

        #pragma unroll
        for (int kt = 0; kt < 8; kt++) {
            const int kc = kt * 16 + 2 * q;
            unsigned a[2][4];
            #pragma unroll
            for (int b = 0; b < 2; b++) {
                const int rb = r0 + 16 * b;
                a[b][0] = *reinterpret_cast<const unsigned*>(feat + rb * SW + kc);
                a[b][1] = *reinterpret_cast<const unsigned*>(feat + (rb + 8) * SW + kc);
                a[b][2] = *reinterpret_cast<const unsigned*>(feat + rb * SW + kc + 8);
                a[b][3] = *reinterpret_cast<const unsigned*>(feat + (rb + 8) * SW + kc + 8);
            }
            #pragma unroll
            for (int t = 0; t < 16; t++) {
                const int n = t * 8 + g4;
                const unsigned b0 = *reinterpret_cast<const unsigned*>(w2t + n * SW + kc);
                const unsigned b1r = *reinterpret_cast<const unsigned*>(w2t + n * SW + kc + 8);
                mma16816(acc[0][t], a[0][0], a[0][1], a[0][2], a[0][3], b0, b1r);
                mma16816(acc[1][t], a[1][0], a[1][1], a[1][2], a[1][3], b0, b1r);
            }
        }

        // ---- epilogue: bias + relu + dot(W3) + lane reduce + sigmoid ----
        #pragma unroll
        for (int b = 0; b < 2; b++) {
            float d0 = 0.f, d1 = 0.f;
            #pragma unroll
            for (int t = 0; t < 16; t++) {
                const int c = t * 8 + 2 * q;
                const float wa = w3s[c], wb = w3s[c + 1];
                d0 += fmaxf(acc[b][t][0] + b2s[c], 0.f) * wa
                    + fmaxf(acc[b][t][1] + b2s[c + 1], 0.f) * wb;
                d1 += fmaxf(acc[b][t][2] + b2s[c], 0.f) * wa
                    + fmaxf(acc[b][t][3] + b2s[c + 1], 0.f) * wb;
            }
            d0 += __shfl_xor_sync(0xFFFFFFFFu, d0, 1);
            d0 += __shfl_xor_sync(0xFFFFFFFFu, d0, 2);
            d1 += __shfl_xor_sync(0xFFFFFFFFu, d1, 1);
            d1 += __shfl_xor_sync(0xFFFFFFFFu, d1, 2);
            if (q == 0) {
                const int e0 = base + r0 + 16 * b;
                const int e1 = e0 + 8;
                if (e0 < E) out[e0] = 1.f / (1.f + __expf(-(d0 + bb3)));
                if (e1 < E) out[e1] = 1.f / (1.f + __expf(-(d1 + bb3)));
            }
        }
        __syncthreads();   // feat reused next tile
    }
}

extern "C" void kernel_launch(void* const* d_in, const int* in_sizes, int n_in,
                              void* d_out, int out_size) {
    const float* node_rep = (const float*)d_in[0];
    const int*   eidx     = (const int*)d_in[1];
    const float* W1       = (const float*)d_in[2];
    const float* b1       = (const float*)d_in[3];
    const float* W2       = (const float*)d_in[4];
    const float* b2       = (const float*)d_in[5];
    const float* W3       = (const float*)d_in[6];
    const float* b3       = (const float*)d_in[7];
    float*       out      = (float*)d_out;

    const int N = in_sizes[0] / 64;
    const int E = in_sizes[1] / 2;
    const int ntiles_pq = (N + 127) / 128;
    const int num_tiles = (E + TILE_M - 1) / TILE_M;

    cudaFuncSetAttribute(pq_precompute,
                         cudaFuncAttributeMaxDynamicSharedMemorySize, PQ_SMEM);
    cudaFuncSetAttribute(graphormer_edge_mlp,
                         cudaFuncAttributeMaxDynamicSharedMemorySize, SMEM_BYTES);

    int g1 = ntiles_pq < 444 ? ntiles_pq : 444;
    pq_precompute<<<g1, THREADS, PQ_SMEM>>>(node_rep, W1, N, ntiles_pq);

    int g2 = num_tiles < 444 ? num_tiles : 444;
    graphormer_edge_mlp<<<g2, THREADS, SMEM_BYTES>>>(
        eidx, b1, W2, b2, W3, b3, out, E, num_tiles);
}

// round 7
// speedup vs baseline: 1.1733x; 1.0214x over previous
#include <cuda_runtime.h>
#include <cuda_bf16.h>
#include <stdint.h>

// Edge MLP, factored: h1[e] = relu(P[src]+Q'[dst]) with P=node@W1[:64], Q'=node@W1[64:]+b1
// (per-node precompute, 100K rows) then per-edge GEMM2 (bf16 HMMA) + dot(W3) + sigmoid.
// R7: h1-build uses packed bf16x2 add/max (was scalar unpack: alu-pipe 26% -> ~12%).

#define TILE_M 128
#define SW 136            // weight/feat smem stride (bf16 elems), conflict-free
#define SWA 72            // A-tile stride in precompute, conflict-free
#define THREADS 128
#define MAX_NODES 100352

__device__ __nv_bfloat16 g_P[(size_t)MAX_NODES * 128];
__device__ __nv_bfloat16 g_Q[(size_t)MAX_NODES * 128];

__device__ __forceinline__ unsigned pack_bf16(float lo, float hi) {
    unsigned r;
    asm("cvt.rn.bf16x2.f32 %0, %1, %2;" : "=r"(r) : "f"(hi), "f"(lo));
    return r;
}
// relu(a + b) on packed bf16x2
__device__ __forceinline__ unsigned add2relu(unsigned a, unsigned b) {
    unsigned r;
    asm("add.rn.bf16x2 %0, %1, %2;" : "=r"(r) : "r"(a), "r"(b));
    asm("max.bf16x2 %0, %0, %1;" : "+r"(r) : "r"(0u));
    return r;
}

__device__ __forceinline__ void mma16816(float c[4],
                                         unsigned a0, unsigned a1, unsigned a2, unsigned a3,
                                         unsigned b0, unsigned b1) {
    asm volatile(
        "mma.sync.aligned.m16n8k16.row.col.f32.bf16.bf16.f32 "
        "{%0,%1,%2,%3}, {%4,%5,%6,%7}, {%8,%9}, {%0,%1,%2,%3};\n"
        : "+f"(c[0]), "+f"(c[1]), "+f"(c[2]), "+f"(c[3])
        : "r"(a0), "r"(a1), "r"(a2), "r"(a3), "r"(b0), "r"(b1));
}

// ---------------- precompute: P = node@W1[:64], Q = node@W1[64:] + b1 ----------------
#define PQ_SMEM_A   (128 * SW * 2)
#define PQ_SMEM_B1  (PQ_SMEM_A + 128 * SWA * 2)
#define PQ_SMEM     (PQ_SMEM_B1 + 128 * 4)

extern "C" __global__ void __launch_bounds__(THREADS, 3)
pq_precompute(const float* __restrict__ node_rep, const float* __restrict__ W1,
              const float* __restrict__ b1, int N, int ntiles) {
    extern __shared__ char smem_raw[];
    __nv_bfloat16* w1t = reinterpret_cast<__nv_bfloat16*>(smem_raw);
    __nv_bfloat16* a   = reinterpret_cast<__nv_bfloat16*>(smem_raw + PQ_SMEM_A);
    float* b1s = reinterpret_cast<float*>(smem_raw + PQ_SMEM_B1);

    const int tid  = threadIdx.x;
    const int lane = tid & 31;
    const int warp = tid >> 5;

    for (int i = tid; i < 128 * 128; i += THREADS) {
        int k = i >> 7, n = i & 127;
        w1t[n * SW + k] = __float2bfloat16(W1[i]);
    }
    if (tid < 128) b1s[tid] = b1[tid];
    __syncthreads();

    const int q  = lane & 3;
    const int g4 = lane >> 2;
    const int r0 = (warp << 5) + g4;

    for (int tile = blockIdx.x; tile < ntiles; tile += gridDim.x) {
        const int base = tile * 128;

        for (int idx = tid; idx < 128 * 16; idx += THREADS) {
            const int row = idx >> 4, seg = idx & 15;
            int node = base + row; if (node >= N) node = N - 1;
            const float4 v = reinterpret_cast<const float4*>(node_rep + (long long)node * 64)[seg];
            const unsigned w0 = pack_bf16(v.x, v.y);
            const unsigned w1p = pack_bf16(v.z, v.w);
            uint64_t dv = ((uint64_t)w1p << 32) | w0;
            *reinterpret_cast<uint64_t*>(a + row * SWA + seg * 4) = dv;
        }
        __syncthreads();

        #pragma unroll
        for (int h = 0; h < 2; h++) {
            float acc[2][16][4];
            #pragma unroll
            for (int b = 0; b < 2; b++)
                #pragma unroll
                for (int t = 0; t < 16; t++)
                    #pragma unroll
                    for (int j = 0; j < 4; j++) acc[b][t][j] = 0.f;

            #pragma unroll
            for (int kt = 0; kt < 4; kt++) {
                const int kc = kt * 16 + 2 * q;
                unsigned af[2][4];
                #pragma unroll
                for (int b = 0; b < 2; b++) {
                    const int rb = r0 + 16 * b;
                    af[b][0] = *reinterpret_cast<const unsigned*>(a + rb * SWA + kc);
                    af[b][1] = *reinterpret_cast<const unsigned*>(a + (rb + 8) * SWA + kc);
                    af[b][2] = *reinterpret_cast<const unsigned*>(a + rb * SWA + kc + 8);
                    af[b][3] = *reinterpret_cast<const unsigned*>(a + (rb + 8) * SWA + kc + 8);
                }
                #pragma unroll
                for (int t = 0; t < 16; t++) {
                    const int n = t * 8 + g4;
                    const unsigned b0 = *reinterpret_cast<const unsigned*>(w1t + n * SW + 64 * h + kc);
                    const unsigned b1r = *reinterpret_cast<const unsigned*>(w1t + n * SW + 64 * h + kc + 8);
                    mma16816(acc[0][t], af[0][0], af[0][1], af[0][2], af[0][3], b0, b1r);
                    mma16816(acc[1][t], af[1][0], af[1][1], af[1][2], af[1][3], b0, b1r);
                }
            }

            __nv_bfloat16* outp = h ? g_Q : g_P;
            const float bsc = h ? 1.f : 0.f;   // fold b1 into Q only
            #pragma unroll
            for (int b = 0; b < 2; b++) {
                const int n0 = base + r0 + 16 * b;
                #pragma unroll
                for (int t = 0; t < 16; t++) {
                    const int c = t * 8 + 2 * q;
                    const float bl = bsc * b1s[c], bh = bsc * b1s[c + 1];
                    if (n0 < N)
                        *reinterpret_cast<unsigned*>(outp + (long long)n0 * 128 + c) =
                            pack_bf16(acc[b][t][0] + bl, acc[b][t][1] + bh);
                    if (n0 + 8 < N)
                        *reinterpret_cast<unsigned*>(outp + (long long)(n0 + 8) * 128 + c) =
                            pack_bf16(acc[b][t][2] + bl, acc[b][t][3] + bh);
                }
            }
        }
        __syncthreads();
    }
}

// ---------------- main: h1 build (bf16x2) + GEMM2 + dot(W3) ----------------
#define SM_W2   0
#define SM_FEAT (128 * SW * 2)
#define SM_F32  (2 * 128 * SW * 2)
#define SMEM_BYTES (SM_F32 + 2 * 128 * 4)

extern "C" __global__ void __launch_bounds__(THREADS, 3)
graphormer_edge_mlp(const int* __restrict__ eidx,
                    const float* __restrict__ W2, const float* __restrict__ b2,
                    const float* __restrict__ W3, const float* __restrict__ b3,
                    float* __restrict__ out,
                    int E, int num_tiles) {
    extern __shared__ char smem_raw[];
    __nv_bfloat16* w2t  = reinterpret_cast<__nv_bfloat16*>(smem_raw + SM_W2);
    __nv_bfloat16* feat = reinterpret_cast<__nv_bfloat16*>(smem_raw + SM_FEAT);
    float* b2s = reinterpret_cast<float*>(smem_raw + SM_F32);
    float* w3s = b2s + 128;

    const int tid  = threadIdx.x;
    const int lane = tid & 31;
    const int warp = tid >> 5;

    for (int i = tid; i < 128 * 128; i += THREADS) {
        int k = i >> 7, n = i & 127;
        w2t[n * SW + k] = __float2bfloat16(W2[i]);
    }
    if (tid < 128) { b2s[tid] = b2[tid]; w3s[tid] = W3[tid]; }
    const float bb3 = b3[0];
    __syncthreads();

    const int q  = lane & 3;
    const int g4 = lane >> 2;
    const int r0 = (warp << 5) + g4;

    for (int tile = blockIdx.x; tile < num_tiles; tile += gridDim.x) {
        const int base = tile * TILE_M;

        // ---- h1 build: relu(P[src] + Q'[dst]) in packed bf16x2 ----
        {
            const int grp = tid >> 4, l16 = tid & 15;
            #pragma unroll
            for (int edge = grp; edge < TILE_M; edge += THREADS / 16) {
                const int e = base + edge;
                int src = 0, dst = 0;
                if (e < E) { src = eidx[e]; dst = eidx[E + e]; }
                const uint4 pv = reinterpret_cast<const uint4*>(g_P + (long long)src * 128)[l16];
                const uint4 qv = reinterpret_cast<const uint4*>(g_Q + (long long)dst * 128)[l16];
                uint4 o;
                o.x = add2relu(pv.x, qv.x);
                o.y = add2relu(pv.y, qv.y);
                o.z = add2relu(pv.z, qv.z);
                o.w = add2relu(pv.w, qv.w);
                *reinterpret_cast<uint4*>(feat + edge * SW + l16 * 8) = o;
            }
        }
        __syncthreads();

        // ---- GEMM2: h1[128,128] @ W2; warp does 2 m16 blocks sharing B frags ----
        float acc[2][16][4];
        #pragma unroll
        for (int b = 0; b < 2; b++)
            #pragma unroll
            for (int t = 0; t < 16; t++)
                #pragma unroll
                for (int j = 0; j < 4; j++) acc[b][t][j] = 0.f;

        #pragma unroll
        for (int kt = 0; kt < 8; kt++) {
            const int kc = kt * 16 + 2 * q;
            unsigned a[2][4];
            #pragma unroll
            for (int b = 0; b < 2; b++) {
                const int rb = r0 + 16 * b;
                a[b][0] = *reinterpret_cast<const unsigned*>(feat + rb * SW + kc);
                a[b][1] = *reinterpret_cast<const unsigned*>(feat + (rb + 8) * SW + kc);
                a[b][2] = *reinterpret_cast<const unsigned*>(feat + rb * SW + kc + 8);
                a[b][3] = *reinterpret_cast<const unsigned*>(feat + (rb + 8) * SW + kc + 8);
            }
            #pragma unroll
            for (int t = 0; t < 16; t++) {
                const int n = t * 8 + g4;
                const unsigned b0 = *reinterpret_cast<const unsigned*>(w2t + n * SW + kc);
                const unsigned b1r = *reinterpret_cast<const unsigned*>(w2t + n * SW + kc + 8);
                mma16816(acc[0][t], a[0][0], a[0][1], a[0][2], a[0][3], b0, b1r);
                mma16816(acc[1][t], a[1][0], a[1][1], a[1][2], a[1][3], b0, b1r);
            }
        }

        // ---- epilogue: bias + relu + dot(W3) + lane reduce + sigmoid ----
        #pragma unroll
        for (int b = 0; b < 2; b++) {
            float d0 = 0.f, d1 = 0.f;
            #pragma unroll
            for (int t = 0; t < 16; t++) {
                const int c = t * 8 + 2 * q;
                const float wa = w3s[c], wb = w3s[c + 1];
                d0 += fmaxf(acc[b][t][0] + b2s[c], 0.f) * wa
                    + fmaxf(acc[b][t][1] + b2s[c + 1], 0.f) * wb;
                d1 += fmaxf(acc[b][t][2] + b2s[c], 0.f) * wa
                    + fmaxf(acc[b][t][3] + b2s[c + 1], 0.f) * wb;
            }
            d0 += __shfl_xor_sync(0xFFFFFFFFu, d0, 1);
            d0 += __shfl_xor_sync(0xFFFFFFFFu, d0, 2);
            d1 += __shfl_xor_sync(0xFFFFFFFFu, d1, 1);
            d1 += __shfl_xor_sync(0xFFFFFFFFu, d1, 2);
            if (q == 0) {
                const int e0 = base + r0 + 16 * b;
                const int e1 = e0 + 8;
                if (e0 < E) out[e0] = 1.f / (1.f + __expf(-(d0 + bb3)));
                if (e1 < E) out[e1] = 1.f / (1.f + __expf(-(d1 + bb3)));
            }
        }
        __syncthreads();
    }
}

extern "C" void kernel_launch(void* const* d_in, const int* in_sizes, int n_in,
                              void* d_out, int out_size) {
    const float* node_rep = (const float*)d_in[0];
    const int*   eidx     = (const int*)d_in[1];
    const float* W1       = (const float*)d_in[2];
    const float* b1       = (const float*)d_in[3];
    const float* W2       = (const float*)d_in[4];
    const float* b2       = (const float*)d_in[5];
    const float* W3       = (const float*)d_in[6];
    const float* b3       = (const float*)d_in[7];
    float*       out      = (float*)d_out;

    const int N = in_sizes[0] / 64;
    const int E = in_sizes[1] / 2;
    const int ntiles_pq = (N + 127) / 128;
    const int num_tiles = (E + TILE_M - 1) / TILE_M;

    cudaFuncSetAttribute(pq_precompute,
                         cudaFuncAttributeMaxDynamicSharedMemorySize, PQ_SMEM);
    cudaFuncSetAttribute(graphormer_edge_mlp,
                         cudaFuncAttributeMaxDynamicSharedMemorySize, SMEM_BYTES);

    int g1 = ntiles_pq < 444 ? ntiles_pq : 444;
    pq_precompute<<<g1, THREADS, PQ_SMEM>>>(node_rep, W1, b1, N, ntiles_pq);

    int g2 = num_tiles < 444 ? num_tiles : 444;
    graphormer_edge_mlp<<<g2, THREADS, SMEM_BYTES>>>(
        eidx, W2, b2, W3, b3, out, E, num_tiles);
}

// round 8
// speedup vs baseline: 1.2331x; 1.0510x over previous
#include <cuda_runtime.h>
#include <cuda_bf16.h>
#include <stdint.h>

// Edge MLP, factored: h1[e] = relu(P[src]+Q'[dst]); P=node@W1[:64], Q'=node@W1[64:]+b1.
// R8: warp-specialized pipeline. Warps 0-3 = GEMM2 consumer, warps 4-7 = gather/h1 producer,
// double-buffered feat tiles, one __syncthreads per tile. Consumer chunks N into 2x64 to
// hold acc in 64 regs (fits 128-reg cap at 256thr x 2 CTA/SM).

#define TILE_M 128
#define SW 136            // w2t stride (bf16 elems), conflict-free (validated R4-R7)
#define SWA 72
#define THREADS 256
#define MAX_NODES 100352

__device__ __nv_bfloat16 g_P[(size_t)MAX_NODES * 128];
__device__ __nv_bfloat16 g_Q[(size_t)MAX_NODES * 128];

__device__ __forceinline__ unsigned pack_bf16(float lo, float hi) {
    unsigned r;
    asm("cvt.rn.bf16x2.f32 %0, %1, %2;" : "=r"(r) : "f"(hi), "f"(lo));
    return r;
}
__device__ __forceinline__ unsigned add2relu(unsigned a, unsigned b) {
    unsigned r;
    asm("add.rn.bf16x2 %0, %1, %2;" : "=r"(r) : "r"(a), "r"(b));
    asm("max.bf16x2 %0, %0, %1;" : "+r"(r) : "r"(0u));
    return r;
}
__device__ __forceinline__ void mma16816(float c[4],
                                         unsigned a0, unsigned a1, unsigned a2, unsigned a3,
                                         unsigned b0, unsigned b1) {
    asm volatile(
        "mma.sync.aligned.m16n8k16.row.col.f32.bf16.bf16.f32 "
        "{%0,%1,%2,%3}, {%4,%5,%6,%7}, {%8,%9}, {%0,%1,%2,%3};\n"
        : "+f"(c[0]), "+f"(c[1]), "+f"(c[2]), "+f"(c[3])
        : "r"(a0), "r"(a1), "r"(a2), "r"(a3), "r"(b0), "r"(b1));
}

// ---------------- precompute: P = node@W1[:64], Q = node@W1[64:] + b1 ----------------
#define PQ_SMEM_A   (128 * SW * 2)
#define PQ_SMEM_B1  (PQ_SMEM_A + 128 * SWA * 2)
#define PQ_SMEM     (PQ_SMEM_B1 + 128 * 4)

extern "C" __global__ void __launch_bounds__(128, 3)
pq_precompute(const float* __restrict__ node_rep, const float* __restrict__ W1,
              const float* __restrict__ b1, int N, int ntiles) {
    extern __shared__ char smem_raw[];
    __nv_bfloat16* w1t = reinterpret_cast<__nv_bfloat16*>(smem_raw);
    __nv_bfloat16* a   = reinterpret_cast<__nv_bfloat16*>(smem_raw + PQ_SMEM_A);
    float* b1s = reinterpret_cast<float*>(smem_raw + PQ_SMEM_B1);

    const int tid  = threadIdx.x;
    const int lane = tid & 31;
    const int warp = tid >> 5;

    for (int i = tid; i < 128 * 128; i += 128) {
        int k = i >> 7, n = i & 127;
        w1t[n * SW + k] = __float2bfloat16(W1[i]);
    }
    if (tid < 128) b1s[tid] = b1[tid];
    __syncthreads();

    const int q  = lane & 3;
    const int g4 = lane >> 2;
    const int r0 = (warp << 5) + g4;

    for (int tile = blockIdx.x; tile < ntiles; tile += gridDim.x) {
        const int base = tile * 128;

        for (int idx = tid; idx < 128 * 16; idx += 128) {
            const int row = idx >> 4, seg = idx & 15;
            int node = base + row; if (node >= N) node = N - 1;
            const float4 v = reinterpret_cast<const float4*>(node_rep + (long long)node * 64)[seg];
            uint64_t dv = ((uint64_t)pack_bf16(v.z, v.w) << 32) | pack_bf16(v.x, v.y);
            *reinterpret_cast<uint64_t*>(a + row * SWA + seg * 4) = dv;
        }
        __syncthreads();

        #pragma unroll
        for (int h = 0; h < 2; h++) {
            float acc[2][16][4];
            #pragma unroll
            for (int b = 0; b < 2; b++)
                #pragma unroll
                for (int t = 0; t < 16; t++)
                    #pragma unroll
                    for (int j = 0; j < 4; j++) acc[b][t][j] = 0.f;

            #pragma unroll
            for (int kt = 0; kt < 4; kt++) {
                const int kc = kt * 16 + 2 * q;
                unsigned af[2][4];
                #pragma unroll
                for (int b = 0; b < 2; b++) {
                    const int rb = r0 + 16 * b;
                    af[b][0] = *reinterpret_cast<const unsigned*>(a + rb * SWA + kc);
                    af[b][1] = *reinterpret_cast<const unsigned*>(a + (rb + 8) * SWA + kc);
                    af[b][2] = *reinterpret_cast<const unsigned*>(a + rb * SWA + kc + 8);
                    af[b][3] = *reinterpret_cast<const unsigned*>(a + (rb + 8) * SWA + kc + 8);
                }
                #pragma unroll
                for (int t = 0; t < 16; t++) {
                    const int n = t * 8 + g4;
                    const unsigned b0 = *reinterpret_cast<const unsigned*>(w1t + n * SW + 64 * h + kc);
                    const unsigned b1r = *reinterpret_cast<const unsigned*>(w1t + n * SW + 64 * h + kc + 8);
                    mma16816(acc[0][t], af[0][0], af[0][1], af[0][2], af[0][3], b0, b1r);
                    mma16816(acc[1][t], af[1][0], af[1][1], af[1][2], af[1][3], b0, b1r);
                }
            }

            __nv_bfloat16* outp = h ? g_Q : g_P;
            const float bsc = h ? 1.f : 0.f;
            #pragma unroll
            for (int b = 0; b < 2; b++) {
                const int n0 = base + r0 + 16 * b;
                #pragma unroll
                for (int t = 0; t < 16; t++) {
                    const int c = t * 8 + 2 * q;
                    const float bl = bsc * b1s[c], bh = bsc * b1s[c + 1];
                    if (n0 < N)
                        *reinterpret_cast<unsigned*>(outp + (long long)n0 * 128 + c) =
                            pack_bf16(acc[b][t][0] + bl, acc[b][t][1] + bh);
                    if (n0 + 8 < N)
                        *reinterpret_cast<unsigned*>(outp + (long long)(n0 + 8) * 128 + c) =
                            pack_bf16(acc[b][t][2] + bl, acc[b][t][3] + bh);
                }
            }
        }
        __syncthreads();
    }
}

// ---------------- main: warp-specialized pipeline ----------------
// smem: w2t [128][SW] bf16; feat[2] double buffer, 256B/row XOR-granule swizzle; b2s,w3s.
#define SM_W2    0
#define SM_FEAT0 34816
#define SM_FEAT1 (34816 + 32768)
#define SM_F32   (34816 + 65536)
#define SMEM_BYTES (SM_F32 + 2 * 128 * 4)

// feat addressing: byte offset = row*256 + ((granule ^ (row&7))<<4) + within
__device__ __forceinline__ uint32_t feat_addr(uint32_t fbase, int row, int gran, int within) {
    return fbase + (uint32_t)row * 256u + (uint32_t)((gran ^ (row & 7)) << 4) + (uint32_t)within;
}

__device__ __forceinline__ uint32_t smem_u32(const void* p) {
    uint32_t a;
    asm("{ .reg .u64 t; cvta.to.shared.u64 t, %1; cvt.u32.u64 %0, t; }" : "=r"(a) : "l"(p));
    return a;
}

extern "C" __global__ void __launch_bounds__(THREADS, 2)
graphormer_edge_mlp(const int* __restrict__ eidx,
                    const float* __restrict__ W2, const float* __restrict__ b2,
                    const float* __restrict__ W3, const float* __restrict__ b3,
                    float* __restrict__ out,
                    int E, int num_tiles) {
    extern __shared__ char smem_raw[];
    __nv_bfloat16* w2t = reinterpret_cast<__nv_bfloat16*>(smem_raw + SM_W2);
    float* b2s = reinterpret_cast<float*>(smem_raw + SM_F32);
    float* w3s = b2s + 128;
    const uint32_t sb = smem_u32(smem_raw);
    const uint32_t fb[2] = { sb + SM_FEAT0, sb + SM_FEAT1 };

    const int tid  = threadIdx.x;
    const int lane = tid & 31;
    const int wid  = tid >> 5;

    for (int i = tid; i < 128 * 128; i += THREADS) {
        int k = i >> 7, n = i & 127;
        w2t[n * SW + k] = __float2bfloat16(W2[i]);
    }
    if (tid < 128) { b2s[tid] = b2[tid]; w3s[tid] = W3[tid]; }
    const float bb3 = b3[0];

    const bool producer = (wid >= 4);
    const int ptid = tid - 128;          // producer-local tid (valid if producer)
    const int grp = ptid >> 4, l16 = ptid & 15;

    const int q  = lane & 3;
    const int g4 = lane >> 2;
    const int r0 = (wid << 5) + g4;      // consumer rows (wid 0-3)

    // ---- prologue: fill buf0 with first tile ----
    __syncthreads();
    if (producer) {
        const int base0 = blockIdx.x * TILE_M;
        #pragma unroll
        for (int edge = grp; edge < TILE_M; edge += 8) {
            const int e = base0 + edge;
            int src = 0, dst = 0;
            if (e < E) { src = eidx[e]; dst = eidx[E + e]; }
            const uint4 pv = reinterpret_cast<const uint4*>(g_P + (long long)src * 128)[l16];
            const uint4 qv = reinterpret_cast<const uint4*>(g_Q + (long long)dst * 128)[l16];
            uint4 o;
            o.x = add2relu(pv.x, qv.x); o.y = add2relu(pv.y, qv.y);
            o.z = add2relu(pv.z, qv.z); o.w = add2relu(pv.w, qv.w);
            const uint32_t ad = feat_addr(fb[0], edge, l16, 0);
            asm volatile("st.shared.v4.b32 [%0], {%1,%2,%3,%4};"
                         :: "r"(ad), "r"(o.x), "r"(o.y), "r"(o.z), "r"(o.w) : "memory");
        }
    }
    __syncthreads();

    int buf = 0;
    for (int tile = blockIdx.x; tile < num_tiles; tile += gridDim.x) {
        if (producer) {
            // ---- fill next tile into other buffer ----
            const int ntile = tile + gridDim.x;
            if (ntile < num_tiles) {
                const int base = ntile * TILE_M;
                #pragma unroll
                for (int edge = grp; edge < TILE_M; edge += 8) {
                    const int e = base + edge;
                    int src = 0, dst = 0;
                    if (e < E) { src = eidx[e]; dst = eidx[E + e]; }
                    const uint4 pv = reinterpret_cast<const uint4*>(g_P + (long long)src * 128)[l16];
                    const uint4 qv = reinterpret_cast<const uint4*>(g_Q + (long long)dst * 128)[l16];
                    uint4 o;
                    o.x = add2relu(pv.x, qv.x); o.y = add2relu(pv.y, qv.y);
                    o.z = add2relu(pv.z, qv.z); o.w = add2relu(pv.w, qv.w);
                    const uint32_t ad = feat_addr(fb[buf ^ 1], edge, l16, 0);
                    asm volatile("st.shared.v4.b32 [%0], {%1,%2,%3,%4};"
                                 :: "r"(ad), "r"(o.x), "r"(o.y), "r"(o.z), "r"(o.w) : "memory");
                }
            }
        } else {
            // ---- consumer: GEMM2 on current buffer, chunked N (2 x 64) ----
            const int base = tile * TILE_M;
            const uint32_t f = fb[buf];
            float dd[2][2];
            dd[0][0] = dd[0][1] = dd[1][0] = dd[1][1] = 0.f;

            #pragma unroll
            for (int ch = 0; ch < 2; ch++) {
                float acc[2][8][4];
                #pragma unroll
                for (int b = 0; b < 2; b++)
                    #pragma unroll
                    for (int t = 0; t < 8; t++)
                        #pragma unroll
                        for (int j = 0; j < 4; j++) acc[b][t][j] = 0.f;

                #pragma unroll
                for (int kt = 0; kt < 8; kt++) {
                    const int kc = kt * 16 + 2 * q;
                    unsigned a[2][4];
                    #pragma unroll
                    for (int b = 0; b < 2; b++) {
                        const int rb = r0 + 16 * b;
                        uint32_t a0 = feat_addr(f, rb,     2 * kt,     4 * q);
                        uint32_t a1 = feat_addr(f, rb + 8, 2 * kt,     4 * q);
                        uint32_t a2 = feat_addr(f, rb,     2 * kt + 1, 4 * q);
                        uint32_t a3 = feat_addr(f, rb + 8, 2 * kt + 1, 4 * q);
                        asm volatile("ld.shared.b32 %0, [%1];" : "=r"(a[b][0]) : "r"(a0));
                        asm volatile("ld.shared.b32 %0, [%1];" : "=r"(a[b][1]) : "r"(a1));
                        asm volatile("ld.shared.b32 %0, [%1];" : "=r"(a[b][2]) : "r"(a2));
                        asm volatile("ld.shared.b32 %0, [%1];" : "=r"(a[b][3]) : "r"(a3));
                    }
                    #pragma unroll
                    for (int t = 0; t < 8; t++) {
                        const int n = (ch * 8 + t) * 8 + g4;
                        const unsigned b0 = *reinterpret_cast<const unsigned*>(w2t + n * SW + kc);
                        const unsigned b1r = *reinterpret_cast<const unsigned*>(w2t + n * SW + kc + 8);
                        mma16816(acc[0][t], a[0][0], a[0][1], a[0][2], a[0][3], b0, b1r);
                        mma16816(acc[1][t], a[1][0], a[1][1], a[1][2], a[1][3], b0, b1r);
                    }
                }

                // partial epilogue for this chunk
                #pragma unroll
                for (int b = 0; b < 2; b++)
                    #pragma unroll
                    for (int t = 0; t < 8; t++) {
                        const int c = (ch * 8 + t) * 8 + 2 * q;
                        const float wa = w3s[c], wb = w3s[c + 1];
                        dd[b][0] += fmaxf(acc[b][t][0] + b2s[c], 0.f) * wa
                                  + fmaxf(acc[b][t][1] + b2s[c + 1], 0.f) * wb;
                        dd[b][1] += fmaxf(acc[b][t][2] + b2s[c], 0.f) * wa
                                  + fmaxf(acc[b][t][3] + b2s[c + 1], 0.f) * wb;
                    }
            }

            #pragma unroll
            for (int b = 0; b < 2; b++) {
                float d0 = dd[b][0], d1 = dd[b][1];
                d0 += __shfl_xor_sync(0xFFFFFFFFu, d0, 1);
                d0 += __shfl_xor_sync(0xFFFFFFFFu, d0, 2);
                d1 += __shfl_xor_sync(0xFFFFFFFFu, d1, 1);
                d1 += __shfl_xor_sync(0xFFFFFFFFu, d1, 2);
                if (q == 0) {
                    const int e0 = base + r0 + 16 * b;
                    const int e1 = e0 + 8;
                    if (e0 < E) out[e0] = 1.f / (1.f + __expf(-(d0 + bb3)));
                    if (e1 < E) out[e1] = 1.f / (1.f + __expf(-(d1 + bb3)));
                }
            }
        }
        __syncthreads();
        buf ^= 1;
    }
}

extern "C" void kernel_launch(void* const* d_in, const int* in_sizes, int n_in,
                              void* d_out, int out_size) {
    const float* node_rep = (const float*)d_in[0];
    const int*   eidx     = (const int*)d_in[1];
    const float* W1       = (const float*)d_in[2];
    const float* b1       = (const float*)d_in[3];
    const float* W2       = (const float*)d_in[4];
    const float* b2       = (const float*)d_in[5];
    const float* W3       = (const float*)d_in[6];
    const float* b3       = (const float*)d_in[7];
    float*       out      = (float*)d_out;

    const int N = in_sizes[0] / 64;
    const int E = in_sizes[1] / 2;
    const int ntiles_pq = (N + 127) / 128;
    const int num_tiles = (E + TILE_M - 1) / TILE_M;

    cudaFuncSetAttribute(pq_precompute,
                         cudaFuncAttributeMaxDynamicSharedMemorySize, PQ_SMEM);
    cudaFuncSetAttribute(graphormer_edge_mlp,
                         cudaFuncAttributeMaxDynamicSharedMemorySize, SMEM_BYTES);

    int g1 = ntiles_pq < 444 ? ntiles_pq : 444;
    pq_precompute<<<g1, 128, PQ_SMEM>>>(node_rep, W1, b1, N, ntiles_pq);

    int g2 = num_tiles < 296 ? num_tiles : 296;
    graphormer_edge_mlp<<<g2, THREADS, SMEM_BYTES>>>(
        eidx, W2, b2, W3, b3, out, E, num_tiles);
}

// round 9
// speedup vs baseline: 1.3079x; 1.0607x over previous
#include <cuda_runtime.h>
#include <cuda_bf16.h>
#include <stdint.h>

// Edge MLP, factored: h1[e] = relu(P[src]+Q'[dst]); P=node@W1[:64], Q'=node@W1[64:]+b1.
// R9: (a) precompute stages P/Q tiles in SMEM and flushes with coalesced uint4 stores
//     (was scattered 4B STG, ~43us); (b) producer batches all edge-index loads before
//     the P/Q gather loads (breaks serial LDG chain that was the per-tile critical path).

#define TILE_M 128
#define SW 136            // stride (bf16 elems), conflict-free
#define SWA 72
#define THREADS 256
#define MAX_NODES 100352

__device__ __nv_bfloat16 g_P[(size_t)MAX_NODES * 128];
__device__ __nv_bfloat16 g_Q[(size_t)MAX_NODES * 128];

__device__ __forceinline__ unsigned pack_bf16(float lo, float hi) {
    unsigned r;
    asm("cvt.rn.bf16x2.f32 %0, %1, %2;" : "=r"(r) : "f"(hi), "f"(lo));
    return r;
}
__device__ __forceinline__ unsigned add2relu(unsigned a, unsigned b) {
    unsigned r;
    asm("add.rn.bf16x2 %0, %1, %2;" : "=r"(r) : "r"(a), "r"(b));
    asm("max.bf16x2 %0, %0, %1;" : "+r"(r) : "r"(0u));
    return r;
}
__device__ __forceinline__ void mma16816(float c[4],
                                         unsigned a0, unsigned a1, unsigned a2, unsigned a3,
                                         unsigned b0, unsigned b1) {
    asm volatile(
        "mma.sync.aligned.m16n8k16.row.col.f32.bf16.bf16.f32 "
        "{%0,%1,%2,%3}, {%4,%5,%6,%7}, {%8,%9}, {%0,%1,%2,%3};\n"
        : "+f"(c[0]), "+f"(c[1]), "+f"(c[2]), "+f"(c[3])
        : "r"(a0), "r"(a1), "r"(a2), "r"(a3), "r"(b0), "r"(b1));
}

// ---------------- precompute: P = node@W1[:64], Q = node@W1[64:] + b1 ----------------
// smem: w1t 34816 | a 18432 | stage 34816 | b1 512
#define PQ_W1    0
#define PQ_A     34816
#define PQ_STAGE (PQ_A + 128 * SWA * 2)
#define PQ_B1    (PQ_STAGE + 128 * SW * 2)
#define PQ_SMEM  (PQ_B1 + 512)

extern "C" __global__ void __launch_bounds__(128, 2)
pq_precompute(const float* __restrict__ node_rep, const float* __restrict__ W1,
              const float* __restrict__ b1, int N, int ntiles) {
    extern __shared__ char smem_raw[];
    __nv_bfloat16* w1t   = reinterpret_cast<__nv_bfloat16*>(smem_raw + PQ_W1);
    __nv_bfloat16* a     = reinterpret_cast<__nv_bfloat16*>(smem_raw + PQ_A);
    __nv_bfloat16* stage = reinterpret_cast<__nv_bfloat16*>(smem_raw + PQ_STAGE);
    float* b1s = reinterpret_cast<float*>(smem_raw + PQ_B1);

    const int tid  = threadIdx.x;
    const int lane = tid & 31;
    const int warp = tid >> 5;

    for (int i = tid; i < 128 * 128; i += 128) {
        int k = i >> 7, n = i & 127;
        w1t[n * SW + k] = __float2bfloat16(W1[i]);
    }
    if (tid < 128) b1s[tid] = b1[tid];
    __syncthreads();

    const int q  = lane & 3;
    const int g4 = lane >> 2;
    const int r0 = (warp << 5) + g4;

    for (int tile = blockIdx.x; tile < ntiles; tile += gridDim.x) {
        const int base = tile * 128;

        for (int idx = tid; idx < 128 * 16; idx += 128) {
            const int row = idx >> 4, seg = idx & 15;
            int node = base + row; if (node >= N) node = N - 1;
            const float4 v = reinterpret_cast<const float4*>(node_rep + (long long)node * 64)[seg];
            uint64_t dv = ((uint64_t)pack_bf16(v.z, v.w) << 32) | pack_bf16(v.x, v.y);
            *reinterpret_cast<uint64_t*>(a + row * SWA + seg * 4) = dv;
        }
        __syncthreads();

        #pragma unroll
        for (int h = 0; h < 2; h++) {
            float acc[2][16][4];
            #pragma unroll
            for (int b = 0; b < 2; b++)
                #pragma unroll
                for (int t = 0; t < 16; t++)
                    #pragma unroll
                    for (int j = 0; j < 4; j++) acc[b][t][j] = 0.f;

            #pragma unroll
            for (int kt = 0; kt < 4; kt++) {
                const int kc = kt * 16 + 2 * q;
                unsigned af[2][4];
                #pragma unroll
                for (int b = 0; b < 2; b++) {
                    const int rb = r0 + 16 * b;
                    af[b][0] = *reinterpret_cast<const unsigned*>(a + rb * SWA + kc);
                    af[b][1] = *reinterpret_cast<const unsigned*>(a + (rb + 8) * SWA + kc);
                    af[b][2] = *reinterpret_cast<const unsigned*>(a + rb * SWA + kc + 8);
                    af[b][3] = *reinterpret_cast<const unsigned*>(a + (rb + 8) * SWA + kc + 8);
                }
                #pragma unroll
                for (int t = 0; t < 16; t++) {
                    const int n = t * 8 + g4;
                    const unsigned b0 = *reinterpret_cast<const unsigned*>(w1t + n * SW + 64 * h + kc);
                    const unsigned b1r = *reinterpret_cast<const unsigned*>(w1t + n * SW + 64 * h + kc + 8);
                    mma16816(acc[0][t], af[0][0], af[0][1], af[0][2], af[0][3], b0, b1r);
                    mma16816(acc[1][t], af[1][0], af[1][1], af[1][2], af[1][3], b0, b1r);
                }
            }

            // ---- stage packed results in SMEM, then coalesced flush to global ----
            const float bsc = h ? 1.f : 0.f;   // fold b1 into Q only
            #pragma unroll
            for (int b = 0; b < 2; b++) {
                const int rr = r0 + 16 * b;
                #pragma unroll
                for (int t = 0; t < 16; t++) {
                    const int c = t * 8 + 2 * q;
                    const float bl = bsc * b1s[c], bh = bsc * b1s[c + 1];
                    *reinterpret_cast<unsigned*>(stage + rr * SW + c) =
                        pack_bf16(acc[b][t][0] + bl, acc[b][t][1] + bh);
                    *reinterpret_cast<unsigned*>(stage + (rr + 8) * SW + c) =
                        pack_bf16(acc[b][t][2] + bl, acc[b][t][3] + bh);
                }
            }
            __syncthreads();

            __nv_bfloat16* outp = h ? g_Q : g_P;
            for (int idx = tid; idx < 128 * 16; idx += 128) {
                const int row = idx >> 4, seg = idx & 15;
                if (base + row < N) {
                    const uint4 v = *reinterpret_cast<const uint4*>(stage + row * SW + seg * 8);
                    *reinterpret_cast<uint4*>(outp + (long long)(base + row) * 128 + seg * 8) = v;
                }
            }
            __syncthreads();
        }
    }
}

// ---------------- main: warp-specialized pipeline ----------------
#define SM_W2    0
#define SM_FEAT0 34816
#define SM_FEAT1 (34816 + 32768)
#define SM_F32   (34816 + 65536)
#define SMEM_BYTES (SM_F32 + 2 * 128 * 4)

__device__ __forceinline__ uint32_t feat_addr(uint32_t fbase, int row, int gran, int within) {
    return fbase + (uint32_t)row * 256u + (uint32_t)((gran ^ (row & 7)) << 4) + (uint32_t)within;
}
__device__ __forceinline__ uint32_t smem_u32(const void* p) {
    uint32_t a;
    asm("{ .reg .u64 t; cvta.to.shared.u64 t, %1; cvt.u32.u64 %0, t; }" : "=r"(a) : "l"(p));
    return a;
}

// producer: fill one 128-edge tile. Index loads batched first (MLP), then gathers.
__device__ __forceinline__ void produce_tile(uint32_t fbase, int base, int E,
                                             const int* __restrict__ eidx,
                                             int grp, int l16) {
    int sidx[16], didx[16];
    #pragma unroll
    for (int i = 0; i < 16; i++) {
        const int e = base + grp + 8 * i;
        const bool v = e < E;
        sidx[i] = v ? eidx[e] : 0;
        didx[i] = v ? eidx[E + e] : 0;
    }
    #pragma unroll
    for (int i = 0; i < 16; i++) {
        const int edge = grp + 8 * i;
        const uint4 pv = reinterpret_cast<const uint4*>(g_P + (long long)sidx[i] * 128)[l16];
        const uint4 qv = reinterpret_cast<const uint4*>(g_Q + (long long)didx[i] * 128)[l16];
        uint4 o;
        o.x = add2relu(pv.x, qv.x); o.y = add2relu(pv.y, qv.y);
        o.z = add2relu(pv.z, qv.z); o.w = add2relu(pv.w, qv.w);
        const uint32_t ad = feat_addr(fbase, edge, l16, 0);
        asm volatile("st.shared.v4.b32 [%0], {%1,%2,%3,%4};"
                     :: "r"(ad), "r"(o.x), "r"(o.y), "r"(o.z), "r"(o.w) : "memory");
    }
}

extern "C" __global__ void __launch_bounds__(THREADS, 2)
graphormer_edge_mlp(const int* __restrict__ eidx,
                    const float* __restrict__ W2, const float* __restrict__ b2,
                    const float* __restrict__ W3, const float* __restrict__ b3,
                    float* __restrict__ out,
                    int E, int num_tiles) {
    extern __shared__ char smem_raw[];
    __nv_bfloat16* w2t = reinterpret_cast<__nv_bfloat16*>(smem_raw + SM_W2);
    float* b2s = reinterpret_cast<float*>(smem_raw + SM_F32);
    float* w3s = b2s + 128;
    const uint32_t sb = smem_u32(smem_raw);
    const uint32_t fb[2] = { sb + SM_FEAT0, sb + SM_FEAT1 };

    const int tid  = threadIdx.x;
    const int lane = tid & 31;
    const int wid  = tid >> 5;

    for (int i = tid; i < 128 * 128; i += THREADS) {
        int k = i >> 7, n = i & 127;
        w2t[n * SW + k] = __float2bfloat16(W2[i]);
    }
    if (tid < 128) { b2s[tid] = b2[tid]; w3s[tid] = W3[tid]; }
    const float bb3 = b3[0];

    const bool producer = (wid >= 4);
    const int ptid = tid - 128;
    const int grp = ptid >> 4, l16 = ptid & 15;

    const int q  = lane & 3;
    const int g4 = lane >> 2;
    const int r0 = (wid << 5) + g4;

    __syncthreads();
    if (producer)
        produce_tile(fb[0], blockIdx.x * TILE_M, E, eidx, grp, l16);
    __syncthreads();

    int buf = 0;
    for (int tile = blockIdx.x; tile < num_tiles; tile += gridDim.x) {
        if (producer) {
            const int ntile = tile + gridDim.x;
            if (ntile < num_tiles)
                produce_tile(fb[buf ^ 1], ntile * TILE_M, E, eidx, grp, l16);
        } else {
            const int base = tile * TILE_M;
            const uint32_t f = fb[buf];
            float dd[2][2];
            dd[0][0] = dd[0][1] = dd[1][0] = dd[1][1] = 0.f;

            #pragma unroll
            for (int ch = 0; ch < 2; ch++) {
                float acc[2][8][4];
                #pragma unroll
                for (int b = 0; b < 2; b++)
                    #pragma unroll
                    for (int t = 0; t < 8; t++)
                        #pragma unroll
                        for (int j = 0; j < 4; j++) acc[b][t][j] = 0.f;

                #pragma unroll
                for (int kt = 0; kt < 8; kt++) {
                    const int kc = kt * 16 + 2 * q;
                    unsigned a[2][4];
                    #pragma unroll
                    for (int b = 0; b < 2; b++) {
                        const int rb = r0 + 16 * b;
                        uint32_t a0 = feat_addr(f, rb,     2 * kt,     4 * q);
                        uint32_t a1 = feat_addr(f, rb + 8, 2 * kt,     4 * q);
                        uint32_t a2 = feat_addr(f, rb,     2 * kt + 1, 4 * q);
                        uint32_t a3 = feat_addr(f, rb + 8, 2 * kt + 1, 4 * q);
                        asm volatile("ld.shared.b32 %0, [%1];" : "=r"(a[b][0]) : "r"(a0));
                        asm volatile("ld.shared.b32 %0, [%1];" : "=r"(a[b][1]) : "r"(a1));
                        asm volatile("ld.shared.b32 %0, [%1];" : "=r"(a[b][2]) : "r"(a2));
                        asm volatile("ld.shared.b32 %0, [%1];" : "=r"(a[b][3]) : "r"(a3));
                    }
                    #pragma unroll
                    for (int t = 0; t < 8; t++) {
                        const int n = (ch * 8 + t) * 8 + g4;
                        const unsigned b0 = *reinterpret_cast<const unsigned*>(w2t + n * SW + kc);
                        const unsigned b1r = *reinterpret_cast<const unsigned*>(w2t + n * SW + kc + 8);
                        mma16816(acc[0][t], a[0][0], a[0][1], a[0][2], a[0][3], b0, b1r);
                        mma16816(acc[1][t], a[1][0], a[1][1], a[1][2], a[1][3], b0, b1r);
                    }
                }

                #pragma unroll
                for (int b = 0; b < 2; b++)
                    #pragma unroll
                    for (int t = 0; t < 8; t++) {
                        const int c = (ch * 8 + t) * 8 + 2 * q;
                        const float wa = w3s[c], wb = w3s[c + 1];
                        dd[b][0] += fmaxf(acc[b][t][0] + b2s[c], 0.f) * wa
                                  + fmaxf(acc[b][t][1] + b2s[c + 1], 0.f) * wb;
                        dd[b][1] += fmaxf(acc[b][t][2] + b2s[c], 0.f) * wa
                                  + fmaxf(acc[b][t][3] + b2s[c + 1], 0.f) * wb;
                    }
            }

            #pragma unroll
            for (int b = 0; b < 2; b++) {
                float d0 = dd[b][0], d1 = dd[b][1];
                d0 += __shfl_xor_sync(0xFFFFFFFFu, d0, 1);
                d0 += __shfl_xor_sync(0xFFFFFFFFu, d0, 2);
                d1 += __shfl_xor_sync(0xFFFFFFFFu, d1, 1);
                d1 += __shfl_xor_sync(0xFFFFFFFFu, d1, 2);
                if (q == 0) {
                    const int e0 = base + r0 + 16 * b;
                    const int e1 = e0 + 8;
                    if (e0 < E) out[e0] = 1.f / (1.f + __expf(-(d0 + bb3)));
                    if (e1 < E) out[e1] = 1.f / (1.f + __expf(-(d1 + bb3)));
                }
            }
        }
        __syncthreads();
        buf ^= 1;
    }
}

extern "C" void kernel_launch(void* const* d_in, const int* in_sizes, int n_in,
                              void* d_out, int out_size) {
    const float* node_rep = (const float*)d_in[0];
    const int*   eidx     = (const int*)d_in[1];
    const float* W1       = (const float*)d_in[2];
    const float* b1       = (const float*)d_in[3];
    const float* W2       = (const float*)d_in[4];
    const float* b2       = (const float*)d_in[5];
    const float* W3       = (const float*)d_in[6];
    const float* b3       = (const float*)d_in[7];
    float*       out      = (float*)d_out;

    const int N = in_sizes[0] / 64;
    const int E = in_sizes[1] / 2;
    const int ntiles_pq = (N + 127) / 128;
    const int num_tiles = (E + TILE_M - 1) / TILE_M;

    cudaFuncSetAttribute(pq_precompute,
                         cudaFuncAttributeMaxDynamicSharedMemorySize, PQ_SMEM);
    cudaFuncSetAttribute(graphormer_edge_mlp,
                         cudaFuncAttributeMaxDynamicSharedMemorySize, SMEM_BYTES);

    int g1 = ntiles_pq < 296 ? ntiles_pq : 296;
    pq_precompute<<<g1, 128, PQ_SMEM>>>(node_rep, W1, b1, N, ntiles_pq);

    int g2 = num_tiles < 296 ? num_tiles : 296;
    graphormer_edge_mlp<<<g2, THREADS, SMEM_BYTES>>>(
        eidx, W2, b2, W3, b3, out, E, num_tiles);
}